// round 2
// baseline (speedup 1.0000x reference)
#include <cuda_runtime.h>
#include <cstdint>

// ---------------------------------------------------------------------------
// Quantized 3x3 SAME conv as exact int8 implicit GEMM.
//   xq = clamp(rint(x*128), -128, 127)   (int8)
//   wq = clamp(rint(w*128), -128, 127)   (int8)
//   acc = sum int8*int8 (int32, exact; |acc| < 2^24)
//   out = (acc >> 7) * 2^-7              (== floor(conv*128)/128, bitwise exact)
// ---------------------------------------------------------------------------

#define BATCH   32
#define HH      112
#define WW      112
#define CIN     64
#define COUT    128
#define NPIX    (BATCH * HH * WW)      // 401408
#define MTILE   128
#define APITCH  80                     // 64B row + 16B pad -> conflict-free LDS
#define WPITCH  80
#define NBLOCKS (NPIX / MTILE)         // 3136
#define W_SMEM  (9 * COUT * WPITCH)    // 92160
#define A_SMEM  (MTILE * APITCH)       // 10240
#define SMEM_TOTAL (W_SMEM + 2 * A_SMEM)  // 112640

// Scratch (device globals: allocation-free rule)
__device__ __align__(16) signed char g_xq[(size_t)NPIX * CIN];   // ~25.7 MB
__device__ __align__(16) signed char g_wq[9 * COUT * CIN];       // [tap][co][ci]

// ---------------------------------------------------------------------------
// Kernel 1: quantize activations  (float4 -> char4, fully coalesced)
// grid covers exactly NPIX*CIN/4 = 6422528 float4s = 25088 blocks * 256
// ---------------------------------------------------------------------------
__global__ void quant_x_kernel(const float4* __restrict__ x) {
    int i = blockIdx.x * blockDim.x + threadIdx.x;
    float4 v = x[i];
    char4 o;
    o.x = (signed char)max(-128, min(127, __float2int_rn(v.x * 128.0f)));
    o.y = (signed char)max(-128, min(127, __float2int_rn(v.y * 128.0f)));
    o.z = (signed char)max(-128, min(127, __float2int_rn(v.z * 128.0f)));
    o.w = (signed char)max(-128, min(127, __float2int_rn(v.w * 128.0f)));
    reinterpret_cast<char4*>(g_xq)[i] = o;
}

// ---------------------------------------------------------------------------
// Kernel 2: quantize + transpose weights HWIO[tap][ci][co] -> [tap][co][ci]
// ---------------------------------------------------------------------------
__global__ void quant_w_kernel(const float* __restrict__ w) {
    int tid = blockIdx.x * blockDim.x + threadIdx.x;   // [tap][co][ci] linear
    int ci  = tid & 63;
    int co  = (tid >> 6) & 127;
    int tap = tid >> 13;
    float v = w[(tap * CIN + ci) * COUT + co];
    g_wq[tid] = (signed char)max(-128, min(127, __float2int_rn(v * 128.0f)));
}

// ---------------------------------------------------------------------------
// mma.sync m16n8k32 s8*s8 -> s32 fragment helpers
// ---------------------------------------------------------------------------
__device__ __forceinline__ void mma_s8(int* c, const uint32_t a[4],
                                       uint32_t b0, uint32_t b1) {
    asm volatile(
        "mma.sync.aligned.m16n8k32.row.col.s32.s8.s8.s32 "
        "{%0,%1,%2,%3}, {%4,%5,%6,%7}, {%8,%9}, {%0,%1,%2,%3};\n"
        : "+r"(c[0]), "+r"(c[1]), "+r"(c[2]), "+r"(c[3])
        : "r"(a[0]), "r"(a[1]), "r"(a[2]), "r"(a[3]), "r"(b0), "r"(b1));
}

__device__ __forceinline__ void cp_async16(uint32_t dst_smem, const void* src,
                                           int src_size) {
    asm volatile("cp.async.cg.shared.global [%0], [%1], 16, %2;\n"
                 :: "r"(dst_smem), "l"(src), "r"(src_size));
}
__device__ __forceinline__ void cp_commit() {
    asm volatile("cp.async.commit_group;\n" ::: "memory");
}
__device__ __forceinline__ void cp_wait_all() {
    asm volatile("cp.async.wait_group 0;\n" ::: "memory");
}

// ---------------------------------------------------------------------------
// Kernel 3: implicit-GEMM conv.
//   CTA: 128 pixels (linear over N*H*W) x 128 cout.  K = 9 taps x 64 ci.
//   Weights resident in smem (padded pitch 80 -> conflict-free LDS).
//   A tile per tap gathered via cp.async w/ zero-fill for SAME-padding OOB,
//   double-buffered: loads for tap t+1 overlap mma of tap t.
//   8 warps = 4 (M) x 2 (N); warp tile 32x64 = 2x2x8 m16n8k32 frags.
// ---------------------------------------------------------------------------
__global__ void __launch_bounds__(256, 2)
conv_kernel(float* __restrict__ out) {
    extern __shared__ signed char smem[];
    signed char* w_s = smem;               // [9*128][80]
    signed char* A_s = smem + W_SMEM;      // 2 x [128][80]

    const int tid    = threadIdx.x;
    const int lane   = tid & 31;
    const int g      = lane >> 2;          // group id (row within 8)
    const int tg     = lane & 3;           // thread in group (k/n sub)
    const int warp   = tid >> 5;
    const int warp_m = warp & 3;           // 0..3, 32 rows each
    const int warp_n = warp >> 2;          // 0..1, 64 cols each

    // ---- weights -> smem (16B chunks into padded rows) ----
    {
        const int4* __restrict__ src = reinterpret_cast<const int4*>(g_wq);
        #pragma unroll
        for (int c = tid; c < 9 * COUT * 4; c += 256) {
            int row = c >> 2, seg = c & 3;
            *reinterpret_cast<int4*>(w_s + row * WPITCH + seg * 16) = src[c];
        }
    }

    // ---- per-thread pixel mapping for the A gather ----
    const int p    = tid >> 1;             // pixel 0..127 (2 threads/pixel)
    const int half = tid & 1;              // bytes [0,32) or [32,64)
    const int P    = blockIdx.x * MTILE + p;
    const int nb   = P / (HH * WW);
    const int hw   = P % (HH * WW);
    const int ph   = hw / WW;
    const int pw   = hw % WW;

    const uint32_t a_base =
        (uint32_t)__cvta_generic_to_shared(A_s) + (uint32_t)(p * APITCH + half * 32);

    auto load_A = [&](int tap, int buf) {
        int dy = tap / 3 - 1, dx = tap % 3 - 1;
        int hh2 = ph + dy, ww2 = pw + dx;
        bool valid = (hh2 >= 0) & (hh2 < HH) & (ww2 >= 0) & (ww2 < WW);
        const signed char* src = valid
            ? g_xq + (((size_t)nb * HH + hh2) * WW + ww2) * CIN + half * 32
            : g_xq;                          // safe addr; src_size=0 zero-fills
        int sz = valid ? 16 : 0;
        uint32_t dst = a_base + (uint32_t)(buf * A_SMEM);
        cp_async16(dst,      src,      sz);
        cp_async16(dst + 16, src + 16, sz);
    };

    int acc[2][8][4];
    #pragma unroll
    for (int mi = 0; mi < 2; mi++)
        #pragma unroll
        for (int nf = 0; nf < 8; nf++)
            #pragma unroll
            for (int r = 0; r < 4; r++) acc[mi][nf][r] = 0;

    // ---- prologue: tap 0 in flight ----
    load_A(0, 0);
    cp_commit();

    #pragma unroll 1
    for (int tap = 0; tap < 9; tap++) {
        const int buf = tap & 1;
        cp_wait_all();          // A(tap) landed
        __syncthreads();        // ...and visible to all; prev compute done

        if (tap < 8) {          // overlap next gather with this tap's mma
            load_A(tap + 1, buf ^ 1);
            cp_commit();
        }

        const signed char* At = A_s + buf * A_SMEM;
        const signed char* Wt = w_s + (size_t)tap * COUT * WPITCH;

        #pragma unroll
        for (int ks = 0; ks < 2; ks++) {          // two k32 steps over ci=64
            uint32_t a[2][4];
            #pragma unroll
            for (int mi = 0; mi < 2; mi++) {
                const signed char* ap =
                    At + (warp_m * 32 + mi * 16 + g) * APITCH + ks * 32 + tg * 4;
                a[mi][0] = *reinterpret_cast<const uint32_t*>(ap);
                a[mi][1] = *reinterpret_cast<const uint32_t*>(ap + 8 * APITCH);
                a[mi][2] = *reinterpret_cast<const uint32_t*>(ap + 16);
                a[mi][3] = *reinterpret_cast<const uint32_t*>(ap + 8 * APITCH + 16);
            }
            #pragma unroll
            for (int nf = 0; nf < 8; nf++) {
                const signed char* bp =
                    Wt + (warp_n * 64 + nf * 8 + g) * WPITCH + ks * 32 + tg * 4;
                uint32_t b0 = *reinterpret_cast<const uint32_t*>(bp);
                uint32_t b1 = *reinterpret_cast<const uint32_t*>(bp + 16);
                mma_s8(acc[0][nf], a[0], b0, b1);
                mma_s8(acc[1][nf], a[1], b0, b1);
            }
        }
    }

    // ---- epilogue: out = (acc >> 7) * 2^-7  (exact floor-quantize) ----
    const float invs = 0.0078125f;
    #pragma unroll
    for (int mi = 0; mi < 2; mi++) {
        const int row0 = warp_m * 32 + mi * 16 + g;
        const size_t base0 = (size_t)(blockIdx.x * MTILE + row0) * COUT;
        #pragma unroll
        for (int nf = 0; nf < 8; nf++) {
            const int col = warp_n * 64 + nf * 8 + tg * 2;
            float2 v0 = make_float2((float)(acc[mi][nf][0] >> 7) * invs,
                                    (float)(acc[mi][nf][1] >> 7) * invs);
            float2 v1 = make_float2((float)(acc[mi][nf][2] >> 7) * invs,
                                    (float)(acc[mi][nf][3] >> 7) * invs);
            *reinterpret_cast<float2*>(out + base0 + col)             = v0;
            *reinterpret_cast<float2*>(out + base0 + 8 * COUT + col)  = v1;
        }
    }
}

// ---------------------------------------------------------------------------
extern "C" void kernel_launch(void* const* d_in, const int* in_sizes, int n_in,
                              void* d_out, int out_size) {
    const float* x = (const float*)d_in[0];       // [32,112,112,64] NHWC
    const float* w = (const float*)d_in[1];       // [3,3,64,128]  HWIO
    float* out = (float*)d_out;                   // [32,112,112,128]

    quant_x_kernel<<<(NPIX * CIN / 4) / 256, 256>>>(
        reinterpret_cast<const float4*>(x));
    quant_w_kernel<<<(9 * COUT * CIN) / 256, 256>>>(w);

    cudaFuncSetAttribute(conv_kernel,
                         cudaFuncAttributeMaxDynamicSharedMemorySize,
                         SMEM_TOTAL);
    conv_kernel<<<NBLOCKS, 256, SMEM_TOTAL>>>(out);
}